// round 2
// baseline (speedup 1.0000x reference)
#include <cuda_runtime.h>

// PhiCell: Phi is identity, so o_t = (x_t - s) + s == x_t (to 1 ulp).
// => outputs = inputs * kernel[0,0]; new_state = outputs[T-1].
// Pure streaming multiply: HBM-bound, ~32 MiB traffic.

__global__ void __launch_bounds__(256) phicell_scale4(
    const float4* __restrict__ in4,
    const float*  __restrict__ kptr,
    float4*       __restrict__ out4,
    int n4)
{
    const float k = __ldg(kptr);
    int i = blockIdx.x * blockDim.x + threadIdx.x;
    if (i < n4) {
        float4 v = in4[i];
        v.x *= k; v.y *= k; v.z *= k; v.w *= k;
        out4[i] = v;
    }
}

// Handles scalar tail (n % 4) and the trailing state slot(s):
// out[j] = in[n-1] * k for all j in [n, out_size).
__global__ void phicell_tail(
    const float* __restrict__ in,
    const float* __restrict__ kptr,
    float*       __restrict__ out,
    int n4x4, int n, int out_size)
{
    const float k = __ldg(kptr);
    int idx = n4x4 + (int)threadIdx.x;
    // scalar remainder of the main array
    if (idx < n) out[idx] = in[idx] * k;
    // state slot(s): final carry == last output
    int j = n + (int)threadIdx.x;
    if (j < out_size) out[j] = in[n - 1] * k;
}

extern "C" void kernel_launch(void* const* d_in, const int* in_sizes, int n_in,
                              void* d_out, int out_size)
{
    const float* in  = (const float*)d_in[0];   // inputs [1, T]
    // d_in[1] = state [1,1] (unused: Phi identity makes output state-independent)
    const float* kpt = (const float*)d_in[2];   // kernel [1,1]
    float* out = (float*)d_out;

    const int n  = in_sizes[0];
    const int n4 = n >> 2;

    if (n4 > 0) {
        const int threads = 256;
        const int blocks  = (n4 + threads - 1) / threads;
        phicell_scale4<<<blocks, threads>>>(
            (const float4*)in, kpt, (float4*)out, n4);
    }
    // tail kernel covers n%4 remainder and state slot(s) past n
    phicell_tail<<<1, 32>>>(in, kpt, out, n4 << 2, n, out_size);
}

// round 3
// speedup vs baseline: 1.1434x; 1.1434x over previous
#include <cuda_runtime.h>

// PhiCell: Phi is identity, so o_t = (x_t - s) + s == x_t (to 1 ulp).
// => outputs = inputs * kernel[0,0]; new_state = outputs[T-1].
// Single fused streaming kernel: one float4 per thread; the thread owning
// the last vector also writes the state slot(s) out[n..out_size).

__global__ void __launch_bounds__(256) phicell_fused(
    const float* __restrict__ in,
    const float* __restrict__ kptr,
    float*       __restrict__ out,
    int n, int out_size)
{
    const float k = __ldg(kptr);
    const int i = blockIdx.x * blockDim.x + threadIdx.x;
    const int base = i << 2;

    if (base + 3 < n) {
        // full vector
        float4 v = *reinterpret_cast<const float4*>(in + base);
        v.x *= k; v.y *= k; v.z *= k; v.w *= k;
        *reinterpret_cast<float4*>(out + base) = v;
        if (base + 4 == n) {
            // this thread holds the final element: write state slot(s)
            for (int j = n; j < out_size; ++j) out[j] = v.w;
        }
    } else if (base < n) {
        // scalar remainder (n % 4 != 0 case; also writes state)
        float last = 0.f;
        for (int idx = base; idx < n; ++idx) {
            last = in[idx] * k;
            out[idx] = last;
        }
        for (int j = n; j < out_size; ++j) out[j] = last;
    }
}

extern "C" void kernel_launch(void* const* d_in, const int* in_sizes, int n_in,
                              void* d_out, int out_size)
{
    const float* in  = (const float*)d_in[0];   // inputs [1, T]
    // d_in[1] = state [1,1] (unused: Phi identity -> output state-independent)
    const float* kpt = (const float*)d_in[2];   // kernel [1,1]
    float* out = (float*)d_out;

    const int n   = in_sizes[0];
    const int nt  = (n + 3) >> 2;               // threads (one float4 each)
    const int thr = 256;
    const int blk = (nt + thr - 1) / thr;

    phicell_fused<<<blk, thr>>>(in, kpt, out, n, out_size);
}

// round 4
// speedup vs baseline: 1.1771x; 1.0295x over previous
#include <cuda_runtime.h>

// PhiCell: Phi is identity => outputs = inputs * k; new_state = outputs[T-1].
// Streaming scale, optimized for MLP: 4 front-batched float4 loads per thread
// (16 elements), block-tiled coalesced layout, single-wave grid.

#define VPT 4  // float4 vectors per thread

__global__ void __launch_bounds__(256) phicell_fused_v4(
    const float4* __restrict__ in4,
    const float*  __restrict__ kptr,
    float4*       __restrict__ out4,
    int n4,                      // number of float4 vectors
    const float* __restrict__ in_scalar,
    float* __restrict__ out_scalar,
    int n, int out_size)
{
    const int tid   = threadIdx.x;
    const int base  = blockIdx.x * (blockDim.x * VPT) + tid;

    // Front-batched loads (independent -> MLP_p1 = 4)
    float4 v[VPT];
    int    idx[VPT];
    bool   ok[VPT];
#pragma unroll
    for (int j = 0; j < VPT; ++j) {
        idx[j] = base + j * (int)blockDim.x;
        ok[j]  = idx[j] < n4;
        if (ok[j]) v[j] = in4[idx[j]];
    }

    const float k = __ldg(kptr);

#pragma unroll
    for (int j = 0; j < VPT; ++j) {
        if (ok[j]) {
            v[j].x *= k; v[j].y *= k; v[j].z *= k; v[j].w *= k;
            out4[idx[j]] = v[j];
            if (idx[j] == n4 - 1 && (n4 << 2) == n) {
                // owner of the final full vector writes state slot(s)
                for (int s = n; s < out_size; ++s) out_scalar[s] = v[j].w;
            }
        }
    }

    // Scalar remainder (n % 4 != 0) + state, handled by one thread of block 0
    if ((n & 3) && blockIdx.x == 0 && tid == 0) {
        float last = 0.f;
        for (int i = n4 << 2; i < n; ++i) {
            last = in_scalar[i] * k;
            out_scalar[i] = last;
        }
        for (int s = n; s < out_size; ++s) out_scalar[s] = last;
    }
}

extern "C" void kernel_launch(void* const* d_in, const int* in_sizes, int n_in,
                              void* d_out, int out_size)
{
    const float* in  = (const float*)d_in[0];   // inputs [1, T]
    // d_in[1] = state [1,1] (unused: Phi identity -> output state-independent)
    const float* kpt = (const float*)d_in[2];   // kernel [1,1]
    float* out = (float*)d_out;

    const int n   = in_sizes[0];
    const int n4  = n >> 2;
    const int thr = 256;
    const int per_block = thr * VPT;            // float4s per block
    const int blk = (n4 + per_block - 1) / per_block;

    phicell_fused_v4<<<blk > 0 ? blk : 1, thr>>>(
        (const float4*)in, kpt, (float4*)out, n4,
        in, out, n, out_size);
}